// round 1
// baseline (speedup 1.0000x reference)
#include <cuda_runtime.h>
#include <cuda_bf16.h>
#include <cstdint>

#define TT   1024
#define BSZ  64
#define DD   256
#define HH   256
#define G4   1024            // 4*H
#define NBLK 128             // persistent recurrent blocks
#define TBH  (TT*BSZ*HH)
#define BH   (BSZ*HH)

// Scratch (device globals: no runtime allocation allowed)
__device__ float    g_Z[(size_t)TT * BSZ * G4];   // [t][b][gate*256+u]  (256 MB)
__device__ float    g_h[2][BSZ * HH];             // double-buffered hidden state
__device__ unsigned g_flags[NBLK];                // per-block step counters

// ---------------------------------------------------------------------------
// Reset flags each launch (graph replays must start clean)
// ---------------------------------------------------------------------------
__global__ void reset_kernel() {
    if (threadIdx.x < NBLK) g_flags[threadIdx.x] = 0u;
}

// ---------------------------------------------------------------------------
// Phase 1: Z[t][b][g*256+u] = bias_g[u] + sum_k x[t][b][k] * W_g[u*512 + k]
// GEMM M=65536 (t*64+b), N=1024, K=256. BM=128, BN=128, BK=16, 8x8 tiles.
// grid = (8, 512): blockIdx.x selects 128 gate-cols (gate fixed per block).
// ---------------------------------------------------------------------------
__global__ __launch_bounds__(256, 2)
void proj_kernel(const float* __restrict__ x,
                 const float* __restrict__ Wf, const float* __restrict__ bf,
                 const float* __restrict__ Wi, const float* __restrict__ bi,
                 const float* __restrict__ Wg, const float* __restrict__ bg,
                 const float* __restrict__ Wo, const float* __restrict__ bo)
{
    __shared__ float As[16 * 132];
    __shared__ float Bs[16 * 132];

    const int tid = threadIdx.x;
    const int tx  = tid & 15;
    const int ty  = tid >> 4;
    const int bm    = blockIdx.y * 128;
    const int gate  = blockIdx.x >> 1;
    const int ucol0 = (blockIdx.x & 1) * 128;

    const float* W    = (gate == 0) ? Wf : (gate == 1) ? Wi : (gate == 2) ? Wg : Wo;
    const float* bias = (gate == 0) ? bf : (gate == 1) ? bi : (gate == 2) ? bg : bo;

    float acc[8][8];
#pragma unroll
    for (int i = 0; i < 8; i++)
#pragma unroll
        for (int j = 0; j < 8; j++) acc[i][j] = 0.f;

    for (int k0 = 0; k0 < 256; k0 += 16) {
#pragma unroll
        for (int it = 0; it < 2; it++) {
            int f4  = tid + it * 256;          // 512 float4 per tile
            int row = f4 >> 2;                 // 0..127
            int kc  = (f4 & 3) << 2;           // 0,4,8,12
            float4 av = *(const float4*)(x + (size_t)(bm + row) * 256 + k0 + kc);
            As[(kc + 0) * 132 + row] = av.x;
            As[(kc + 1) * 132 + row] = av.y;
            As[(kc + 2) * 132 + row] = av.z;
            As[(kc + 3) * 132 + row] = av.w;
            float4 bv = *(const float4*)(W + (size_t)(ucol0 + row) * 512 + k0 + kc);
            Bs[(kc + 0) * 132 + row] = bv.x;
            Bs[(kc + 1) * 132 + row] = bv.y;
            Bs[(kc + 2) * 132 + row] = bv.z;
            Bs[(kc + 3) * 132 + row] = bv.w;
        }
        __syncthreads();
#pragma unroll
        for (int kk = 0; kk < 16; kk++) {
            float4 a0 = *(const float4*)&As[kk * 132 + ty * 8];
            float4 a1 = *(const float4*)&As[kk * 132 + ty * 8 + 4];
            float4 b0 = *(const float4*)&Bs[kk * 132 + tx * 8];
            float4 b1 = *(const float4*)&Bs[kk * 132 + tx * 8 + 4];
            float a[8] = {a0.x, a0.y, a0.z, a0.w, a1.x, a1.y, a1.z, a1.w};
            float b[8] = {b0.x, b0.y, b0.z, b0.w, b1.x, b1.y, b1.z, b1.w};
#pragma unroll
            for (int i = 0; i < 8; i++)
#pragma unroll
                for (int j = 0; j < 8; j++) acc[i][j] += a[i] * b[j];
        }
        __syncthreads();
    }

    float4 q0 = *(const float4*)(bias + ucol0 + tx * 8);
    float4 q1 = *(const float4*)(bias + ucol0 + tx * 8 + 4);
    float bb[8] = {q0.x, q0.y, q0.z, q0.w, q1.x, q1.y, q1.z, q1.w};

#pragma unroll
    for (int i = 0; i < 8; i++) {
        size_t m  = (size_t)(bm + ty * 8 + i);
        float* zp = g_Z + m * 1024 + gate * 256 + ucol0 + tx * 8;
        float4 v0 = {acc[i][0] + bb[0], acc[i][1] + bb[1], acc[i][2] + bb[2], acc[i][3] + bb[3]};
        float4 v1 = {acc[i][4] + bb[4], acc[i][5] + bb[5], acc[i][6] + bb[6], acc[i][7] + bb[7]};
        *(float4*)zp       = v0;
        *(float4*)(zp + 4) = v1;
    }
}

// ---------------------------------------------------------------------------
// Phase 2: persistent recurrence. 128 blocks x 256 threads, all co-resident.
// Block `blk` owns hidden units {2*blk, 2*blk+1} -> 8 gate columns.
// lane = kq*8 + c : kq in [0,4) = K-quarter (64 k's), c = gate-col (g*2+v).
// Recurrent weights: 16 float4 in registers per lane, loaded once.
// warp w handles batches [8w, 8w+8). h read directly from L2 (LDG.128,
// 8-way broadcast coalesced). Reduce over kq with 2 shfl_xor.
// ---------------------------------------------------------------------------
__device__ __forceinline__ float sig_(float v)  { return __fdividef(1.f, 1.f + __expf(-v)); }
__device__ __forceinline__ float tanh_(float v) { return __fdividef(2.f, 1.f + __expf(-2.f * v)) - 1.f; }

__global__ __launch_bounds__(256, 1)
void lstm_kernel(const float* __restrict__ Wf, const float* __restrict__ Wi,
                 const float* __restrict__ Wg, const float* __restrict__ Wo,
                 float* __restrict__ out)
{
    __shared__ float pre[8 * 65];   // [c][b], stride 65 -> conflict-free

    const int tid  = threadIdx.x;
    const int blk  = blockIdx.x;
    const int u0   = blk * 2;
    const int lane = tid & 31;
    const int warp = tid >> 5;
    const int kq   = lane >> 3;
    const int c    = lane & 7;
    const int g    = c >> 1;
    const int v    = c & 1;
    const int u    = u0 + v;

    const float* Wsel = (g == 0) ? Wf : (g == 1) ? Wi : (g == 2) ? Wg : Wo;
    const float4* wrow = (const float4*)(Wsel + (size_t)u * 512 + 256 + kq * 64);
    float4 wr[16];
#pragma unroll
    for (int i = 0; i < 16; i++) wr[i] = wrow[i];

    // epilogue identity (threads 0..127): v_e in {0,1}, b_e in [0,64)
    const int v_e = tid >> 6;
    const int b_e = tid & 63;
    const int u_e = u0 + v_e;
    float cstate = 0.f;

    for (int t = 0; t < TT; t++) {
        // Prefetch Z (independent of h) before waiting on flags
        float z0 = 0.f, z1 = 0.f, z2 = 0.f, z3 = 0.f;
        if (tid < 128) {
            const float* zr = g_Z + ((size_t)t * 64 + b_e) * 1024 + u_e;
            z0 = zr[0]; z1 = zr[256]; z2 = zr[512]; z3 = zr[768];
        }

        // Wait for all blocks to have published h_t
        if (t > 0 && tid < NBLK) {
            const volatile unsigned* fp = (const volatile unsigned*)&g_flags[tid];
            while (*fp < (unsigned)t) __nanosleep(32);
            __threadfence();   // acquire: order subsequent h reads after flag
        }
        __syncthreads();

        if (t > 0) {
            const float* hprev = g_h[t & 1];
#pragma unroll 2
            for (int b8 = 0; b8 < 8; b8++) {
                int bb = warp * 8 + b8;
                const float4* hb = (const float4*)(hprev + bb * 256 + kq * 64);
                float ax = 0.f, ay = 0.f, az = 0.f, aw = 0.f;
#pragma unroll
                for (int it = 0; it < 16; it++) {
                    float4 h4 = hb[it];
                    ax += h4.x * wr[it].x;
                    ay += h4.y * wr[it].y;
                    az += h4.z * wr[it].z;
                    aw += h4.w * wr[it].w;
                }
                float p = (ax + ay) + (az + aw);
                p += __shfl_xor_sync(0xffffffffu, p, 8);
                p += __shfl_xor_sync(0xffffffffu, p, 16);
                if (kq == 0) pre[c * 65 + bb] = p;
            }
        } else {
            if (kq == 0) {
#pragma unroll
                for (int b8 = 0; b8 < 8; b8++) pre[c * 65 + warp * 8 + b8] = 0.f;
            }
        }
        __syncthreads();

        if (tid < 128) {
            float fg = sig_ (pre[(0 + v_e) * 65 + b_e] + z0);
            float ig = sig_ (pre[(2 + v_e) * 65 + b_e] + z1);
            float gg = tanh_(pre[(4 + v_e) * 65 + b_e] + z2);
            float og = sig_ (pre[(6 + v_e) * 65 + b_e] + z3);
            cstate = fg * cstate + ig * gg;
            float h = og * tanh_(cstate);
            g_h[(t + 1) & 1][b_e * 256 + u_e]        = h;
            out[((size_t)t * 64 + b_e) * 256 + u_e]  = h;
            if (t == TT - 1) {
                out[TBH + b_e * 256 + u_e]      = h;       // hx
                out[TBH + BH + b_e * 256 + u_e] = cstate;  // cx
            }
        }

        __threadfence();       // release: h writes visible before flag bump
        __syncthreads();
        if (tid == 0) {
            *(volatile unsigned*)&g_flags[blk] = (unsigned)(t + 1);
        }
    }
}

// ---------------------------------------------------------------------------
// Launch
// ---------------------------------------------------------------------------
extern "C" void kernel_launch(void* const* d_in, const int* in_sizes, int n_in,
                              void* d_out, int out_size)
{
    const float* x  = (const float*)d_in[0];
    const float* Wf = (const float*)d_in[1];
    const float* bf = (const float*)d_in[2];
    const float* Wi = (const float*)d_in[3];
    const float* bi = (const float*)d_in[4];
    const float* Wg = (const float*)d_in[5];
    const float* bg = (const float*)d_in[6];
    const float* Wo = (const float*)d_in[7];
    const float* bo = (const float*)d_in[8];
    float* out = (float*)d_out;

    reset_kernel<<<1, 128>>>();
    proj_kernel<<<dim3(8, 512), 256>>>(x, Wf, bf, Wi, bi, Wg, bg, Wo, bo);
    lstm_kernel<<<NBLK, 256>>>(Wf, Wi, Wg, Wo, out);
}

// round 4
// speedup vs baseline: 1.8922x; 1.8922x over previous
#include <cuda_runtime.h>
#include <cuda_bf16.h>
#include <cstdint>

#define TT   1024
#define BSZ  64
#define DD   256
#define HH   256
#define G4   1024            // 4*H
#define NBLK 128             // persistent recurrent blocks
#define TBH  (TT*BSZ*HH)
#define BH   (BSZ*HH)

// Scratch (device globals: no runtime allocation allowed)
__device__ float    g_Z[(size_t)TT * BSZ * G4];   // [t][b][gate*256+u]  (256 MB)
__device__ float    g_h[2][BSZ * HH];             // double-buffered hidden state
__device__ unsigned g_cnt;                        // global step counter (release/acquire)

// ---------------------------------------------------------------------------
// Phase 1: Z[t][b][g*256+u] = bias_g[u] + sum_k x[t][b][k] * W_g[u*512 + k]
// GEMM M=65536 (t*64+b), N=1024, K=256. BM=128, BN=128, BK=16, 8x8 tiles.
// Also resets g_cnt (runs fully before lstm due to stream ordering).
// ---------------------------------------------------------------------------
__global__ __launch_bounds__(256, 2)
void proj_kernel(const float* __restrict__ x,
                 const float* __restrict__ Wf, const float* __restrict__ bf,
                 const float* __restrict__ Wi, const float* __restrict__ bi,
                 const float* __restrict__ Wg, const float* __restrict__ bg,
                 const float* __restrict__ Wo, const float* __restrict__ bo)
{
    __shared__ float As[16 * 132];
    __shared__ float Bs[16 * 132];

    const int tid = threadIdx.x;
    if (blockIdx.x == 0 && blockIdx.y == 0 && tid == 0) g_cnt = 0u;

    const int tx  = tid & 15;
    const int ty  = tid >> 4;
    const int bm    = blockIdx.y * 128;
    const int gate  = blockIdx.x >> 1;
    const int ucol0 = (blockIdx.x & 1) * 128;

    const float* W    = (gate == 0) ? Wf : (gate == 1) ? Wi : (gate == 2) ? Wg : Wo;
    const float* bias = (gate == 0) ? bf : (gate == 1) ? bi : (gate == 2) ? bg : bo;

    float acc[8][8];
#pragma unroll
    for (int i = 0; i < 8; i++)
#pragma unroll
        for (int j = 0; j < 8; j++) acc[i][j] = 0.f;

    for (int k0 = 0; k0 < 256; k0 += 16) {
#pragma unroll
        for (int it = 0; it < 2; it++) {
            int f4  = tid + it * 256;          // 512 float4 per tile
            int row = f4 >> 2;                 // 0..127
            int kc  = (f4 & 3) << 2;           // 0,4,8,12
            float4 av = *(const float4*)(x + (size_t)(bm + row) * 256 + k0 + kc);
            As[(kc + 0) * 132 + row] = av.x;
            As[(kc + 1) * 132 + row] = av.y;
            As[(kc + 2) * 132 + row] = av.z;
            As[(kc + 3) * 132 + row] = av.w;
            float4 bv = *(const float4*)(W + (size_t)(ucol0 + row) * 512 + k0 + kc);
            Bs[(kc + 0) * 132 + row] = bv.x;
            Bs[(kc + 1) * 132 + row] = bv.y;
            Bs[(kc + 2) * 132 + row] = bv.z;
            Bs[(kc + 3) * 132 + row] = bv.w;
        }
        __syncthreads();
#pragma unroll
        for (int kk = 0; kk < 16; kk++) {
            float4 a0 = *(const float4*)&As[kk * 132 + ty * 8];
            float4 a1 = *(const float4*)&As[kk * 132 + ty * 8 + 4];
            float4 b0 = *(const float4*)&Bs[kk * 132 + tx * 8];
            float4 b1 = *(const float4*)&Bs[kk * 132 + tx * 8 + 4];
            float a[8] = {a0.x, a0.y, a0.z, a0.w, a1.x, a1.y, a1.z, a1.w};
            float b[8] = {b0.x, b0.y, b0.z, b0.w, b1.x, b1.y, b1.z, b1.w};
#pragma unroll
            for (int i = 0; i < 8; i++)
#pragma unroll
                for (int j = 0; j < 8; j++) acc[i][j] += a[i] * b[j];
        }
        __syncthreads();
    }

    float4 q0 = *(const float4*)(bias + ucol0 + tx * 8);
    float4 q1 = *(const float4*)(bias + ucol0 + tx * 8 + 4);
    float bb[8] = {q0.x, q0.y, q0.z, q0.w, q1.x, q1.y, q1.z, q1.w};

#pragma unroll
    for (int i = 0; i < 8; i++) {
        size_t m  = (size_t)(bm + ty * 8 + i);
        float* zp = g_Z + m * 1024 + gate * 256 + ucol0 + tx * 8;
        float4 v0 = {acc[i][0] + bb[0], acc[i][1] + bb[1], acc[i][2] + bb[2], acc[i][3] + bb[3]};
        float4 v1 = {acc[i][4] + bb[4], acc[i][5] + bb[5], acc[i][6] + bb[6], acc[i][7] + bb[7]};
        *(float4*)zp       = v0;
        *(float4*)(zp + 4) = v1;
    }
}

// ---------------------------------------------------------------------------
// Phase 2: persistent recurrence. 128 blocks x 512 threads, all co-resident.
// Block `blk` owns hidden units {2*blk, 2*blk+1} -> 8 gate columns.
// Per step: stage full h (64KB) into padded SMEM (8 LDG.128/thread, __ldcg),
// then FFMA GEMM from SMEM (conflict-free), shfl-reduce, epilogue on 64
// threads (float2), sync via single release/acquire counter in L2.
// lane = kq*8 + c : kq = K-quarter (64 k's), c = gate-col (g*2+v).
// warp w handles batches [4w, 4w+4) (16 warps).
// SMEM h layout: hs[kq*4100 + b*64 + j]  (kq-stride 16400B = 16 mod 128 ->
// the 4 kq addresses per wavefront land in distinct 16B segments).
// ---------------------------------------------------------------------------
__device__ __forceinline__ float sig_(float v)  { return __fdividef(1.f, 1.f + __expf(-v)); }
__device__ __forceinline__ float tanh_(float v) { return __fdividef(2.f, 1.f + __expf(-2.f * v)) - 1.f; }

#define HS_FLOATS (4 * 4100)
#define PRE_OFF   HS_FLOATS            // pre[8*65] after hs
#define SMEM_FLOATS (HS_FLOATS + 8 * 65)

__global__ __launch_bounds__(512, 1)
void lstm_kernel(const float* __restrict__ Wf, const float* __restrict__ Wi,
                 const float* __restrict__ Wg, const float* __restrict__ Wo,
                 float* __restrict__ out)
{
    extern __shared__ float smem[];
    float* hs  = smem;
    float* pre = smem + PRE_OFF;       // [c][b], stride 65 -> conflict-free

    const int tid  = threadIdx.x;
    const int blk  = blockIdx.x;
    const int u0   = blk * 2;
    const int lane = tid & 31;
    const int warp = tid >> 5;
    const int kq   = lane >> 3;
    const int c    = lane & 7;
    const int g    = c >> 1;
    const int v    = c & 1;
    const int u    = u0 + v;

    const float* Wsel = (g == 0) ? Wf : (g == 1) ? Wi : (g == 2) ? Wg : Wo;
    const float4* wrow = (const float4*)(Wsel + (size_t)u * 512 + 256 + kq * 64);
    float4 wr[16];
#pragma unroll
    for (int i = 0; i < 16; i++) wr[i] = wrow[i];

    float2 cst = {0.f, 0.f};

    for (int t = 0; t < TT; t++) {
        // Prefetch Z (independent of h) before waiting on the counter
        float2 zf, zi, zg, zo;
        if (tid < 64) {
            const float* zr = g_Z + ((size_t)t * 64 + tid) * 1024 + u0;
            zf = __ldcs((const float2*)(zr));
            zi = __ldcs((const float2*)(zr + 256));
            zg = __ldcs((const float2*)(zr + 512));
            zo = __ldcs((const float2*)(zr + 768));
        }

        if (t > 0) {
            // Acquire: wait for all 128 blocks to have finished step t-1
            if (tid == 0) {
                unsigned target = (unsigned)(NBLK * t);
                unsigned vv;
                do {
                    asm volatile("ld.acquire.gpu.global.u32 %0, [%1];"
                                 : "=r"(vv) : "l"(&g_cnt) : "memory");
                } while (vv < target);
            }
            __syncthreads();

            // Stage h -> SMEM (8 x LDG.128 per thread, L2-coherent)
            const float* hsrc = g_h[t & 1];
#pragma unroll
            for (int i = 0; i < 8; i++) {
                int f4 = tid + i * 512;        // 4096 float4 total
                int b  = f4 >> 6;
                int k4 = f4 & 63;
                int kqi = k4 >> 4;
                int j4  = k4 & 15;
                float4 hv = __ldcg((const float4*)(hsrc + b * 256 + k4 * 4));
                *(float4*)&hs[kqi * 4100 + b * 64 + j4 * 4] = hv;
            }
            __syncthreads();

            // GEMM: each lane -> one gate-col, one K-quarter; 4 batches/warp
#pragma unroll
            for (int b4 = 0; b4 < 4; b4++) {
                int bb = warp * 4 + b4;
                const float4* hb = (const float4*)&hs[kq * 4100 + bb * 64];
                float ax = 0.f, ay = 0.f, az = 0.f, aw = 0.f;
#pragma unroll
                for (int it = 0; it < 16; it++) {
                    float4 h4 = hb[it];
                    ax += h4.x * wr[it].x;
                    ay += h4.y * wr[it].y;
                    az += h4.z * wr[it].z;
                    aw += h4.w * wr[it].w;
                }
                float p = (ax + ay) + (az + aw);
                p += __shfl_xor_sync(0xffffffffu, p, 8);
                p += __shfl_xor_sync(0xffffffffu, p, 16);
                if (kq == 0) pre[c * 65 + bb] = p;
            }
        } else {
            if (tid < 64) {
#pragma unroll
                for (int cc = 0; cc < 8; cc++) pre[cc * 65 + tid] = 0.f;
            }
        }
        __syncthreads();

        if (tid < 64) {
            const int b_e = tid;
            float f0 = sig_ (pre[0 * 65 + b_e] + zf.x);
            float f1 = sig_ (pre[1 * 65 + b_e] + zf.y);
            float i0 = sig_ (pre[2 * 65 + b_e] + zi.x);
            float i1 = sig_ (pre[3 * 65 + b_e] + zi.y);
            float g0 = tanh_(pre[4 * 65 + b_e] + zg.x);
            float g1 = tanh_(pre[5 * 65 + b_e] + zg.y);
            float o0 = sig_ (pre[6 * 65 + b_e] + zo.x);
            float o1 = sig_ (pre[7 * 65 + b_e] + zo.y);
            cst.x = f0 * cst.x + i0 * g0;
            cst.y = f1 * cst.y + i1 * g1;
            float2 h2 = {o0 * tanh_(cst.x), o1 * tanh_(cst.y)};
            *(float2*)&g_h[(t + 1) & 1][b_e * 256 + u0]       = h2;
            *(float2*)&out[((size_t)t * 64 + b_e) * 256 + u0] = h2;
            if (t == TT - 1) {
                *(float2*)&out[TBH + b_e * 256 + u0]      = h2;
                *(float2*)&out[TBH + BH + b_e * 256 + u0] = cst;
            }
        }

        __syncthreads();     // epilogue stores done before release
        if (tid == 0) {
            asm volatile("red.release.gpu.global.add.u32 [%0], %1;"
                         :: "l"(&g_cnt), "r"(1u) : "memory");
        }
    }
}

// ---------------------------------------------------------------------------
// Launch
// ---------------------------------------------------------------------------
extern "C" void kernel_launch(void* const* d_in, const int* in_sizes, int n_in,
                              void* d_out, int out_size)
{
    const float* x  = (const float*)d_in[0];
    const float* Wf = (const float*)d_in[1];
    const float* bf = (const float*)d_in[2];
    const float* Wi = (const float*)d_in[3];
    const float* bi = (const float*)d_in[4];
    const float* Wg = (const float*)d_in[5];
    const float* bg = (const float*)d_in[6];
    const float* Wo = (const float*)d_in[7];
    const float* bo = (const float*)d_in[8];
    float* out = (float*)d_out;

    static bool attr_set = false;
    if (!attr_set) {
        cudaFuncSetAttribute(lstm_kernel,
                             cudaFuncAttributeMaxDynamicSharedMemorySize,
                             SMEM_FLOATS * (int)sizeof(float));
        attr_set = true;
    }

    proj_kernel<<<dim3(8, 512), 256>>>(x, Wf, bf, Wi, bi, Wg, bg, Wo, bo);
    lstm_kernel<<<NBLK, 512, SMEM_FLOATS * sizeof(float)>>>(Wf, Wi, Wg, Wo, out);
}